// round 14
// baseline (speedup 1.0000x reference)
#include <cuda_runtime.h>

#define BB 8
#define N1V 50176
#define N2V 12544
#define N3V 3136
#define CNT 100352          // BB*N2V
#define BN_EPS 1e-5f

typedef unsigned long long ull;

// ---------------- scratch ----------------
__device__ float d_xt1[N1V * 24];
__device__ float d_A1[N2V * 81];
__device__ float d_A2[N2V * 81];
__device__ float d_y1[N2V * 256];   // RAW outputs; BN fused into consumers
__device__ float d_y2[N2V * 256];
__device__ float d_y3[N2V * 512];
__device__ float d_stats[256];      // s1[32] q1[32] s2[32] q2[32] s3[64] q3[64]

// ---------------- f32x2 helpers ----------------
__device__ __forceinline__ ull pack2(float lo, float hi) {
    ull r; asm("mov.b64 %0, {%1, %2};" : "=l"(r) : "f"(lo), "f"(hi)); return r;
}
__device__ __forceinline__ void unpack2(ull v, float& lo, float& hi) {
    asm("mov.b64 {%0, %1}, %2;" : "=f"(lo), "=f"(hi) : "l"(v));
}
__device__ __forceinline__ ull ffma2(ull a, ull b, ull c) {
    ull d; asm("fma.rn.f32x2 %0, %1, %2, %3;" : "=l"(d) : "l"(a), "l"(b), "l"(c)); return d;
}

// ---------------- transpose x (8,3,N1) -> xt1[n][24]; block 0 zeros stats ----------------
__global__ void k_transpose(const float* __restrict__ x, float* __restrict__ xt,
                            float* __restrict__ stats) {
    int tid = threadIdx.x;
    if (blockIdx.x == 0) stats[tid] = 0.f;
    int n = blockIdx.x * 256 + tid;
    if (n >= N1V) return;
    float4 t4[6];
    float* t = (float*)t4;
#pragma unroll
    for (int bc = 0; bc < 24; ++bc) t[bc] = x[bc * N1V + n];
    float4* dst = (float4*)(xt + n * 24);
#pragma unroll
    for (int i = 0; i < 6; ++i) dst[i] = t4[i];
}

// ---------------- weight MLP (both offsets, one launch) ----------------
__global__ void __launch_bounds__(128) k_mlp2(const float* __restrict__ off1,
                      const float* __restrict__ off2,
                      const float* __restrict__ Wh, const float* __restrict__ bh,
                      const float* __restrict__ Wo, const float* __restrict__ bo,
                      float* __restrict__ A1, float* __restrict__ A2) {
    __shared__ float sWh[64], sbh[32], sWo[288], sbo[9];
    int tid = threadIdx.x;
    if (tid < 64) sWh[tid] = Wh[tid];
    if (tid < 32) sbh[tid] = bh[tid];
    for (int e = tid; e < 288; e += 128) sWo[e] = Wo[e];
    if (tid < 9) sbo[tid] = bo[tid];
    __syncthreads();
    int id = blockIdx.x * 128 + tid;
    const int T9 = N2V * 9;
    if (id >= 2 * T9) return;
    const float* off = (id < T9) ? off1 : off2;
    float* A = (id < T9) ? A1 : A2;
    int lid = (id < T9) ? id : id - T9;
    float2 o2 = ((const float2*)off)[lid];
    float h[32];
#pragma unroll
    for (int j = 0; j < 32; ++j)
        h[j] = fmaxf(0.f, fmaf(o2.x, sWh[j], fmaf(o2.y, sWh[32 + j], sbh[j])));
#pragma unroll
    for (int t = 0; t < 9; ++t) {
        float acc = sbo[t];
#pragma unroll
        for (int j = 0; j < 32; ++j) acc = fmaf(h[j], sWo[j * 9 + t], acc);
        A[lid * 9 + t] = acc;
    }
}

// ---------------- fused interp-conv layer ----------------
// CTA computes ONB=32 output cols at obase (SPLIT2: obase=(blockIdx&1)*32).
// Stage B: vectorized float4 gather (NQ=4, CQ=8), thread=(pt,cq,b).
// G TRANSPOSED sm_G[ct*RS+row]. Stage C: 4 col-tiles x 2 row-halves over 8 warps
// (OT=8 warp-uniform W broadcast, RT=2 rows/lane, G contiguous float2).
template <int C, int OFULL, int NQ, int RS, bool BNIN, bool SPLIT2>
__global__ void __launch_bounds__(256, 2) k_layer(
    const float* __restrict__ xin, const float* __restrict__ A,
    const int* __restrict__ nbr, const float* __restrict__ Wg,
    const float* __restrict__ bias, float* __restrict__ yout,
    float* __restrict__ gSum, float* __restrict__ gSq,
    const float* __restrict__ pS, const float* __restrict__ pQ,
    const float* __restrict__ pG, const float* __restrict__ pB)
{
    constexpr int ONB = 32;
    constexpr int OT = 8;
    constexpr int RT = 2;
    constexpr int P = 16;
    constexpr int BCin = BB * C;
    constexpr int CT = C * 9;
    constexpr int CQ = C / NQ;         // 8 for C=32
    constexpr int CTQ = CQ * 9;
    constexpr int NG = N2V / P;        // 784

    extern __shared__ float sm[];
    float* sm_Wt  = sm;                       // CT*ONB
    float* sm_G   = sm_Wt + CT * ONB;         // CTQ*RS
    float* sm_a   = sm_G + CTQ * RS;          // P*108
    float* sm_bias= sm_a + P * 108;           // ONB
    float* sm_sum = sm_bias + ONB;            // ONB
    float* sm_sq  = sm_sum + ONB;             // ONB
    float* sm_sc  = sm_sq + ONB;              // C
    float* sm_sh  = sm_sc + C;                // C
    int*   sm_idx = (int*)(sm_sh + C);        // P*9

    const int tid = threadIdx.x;

    int obase = 0, g0 = blockIdx.x, gstride = gridDim.x;
    if (SPLIT2) { obase = (blockIdx.x & 1) * ONB; g0 = blockIdx.x >> 1; gstride = gridDim.x >> 1; }

    for (int e = tid; e < CT * ONB; e += 256) {
        int ct = e / ONB, ol = e - ct * ONB;
        sm_Wt[e] = Wg[(obase + ol) * CT + ct];
    }
    if (tid < ONB) { sm_bias[tid] = bias[obase + tid]; sm_sum[tid] = 0.f; sm_sq[tid] = 0.f; }
    if (BNIN && tid < C) {
        float mean = pS[tid] * (1.f / CNT);
        float var  = pQ[tid] * (1.f / CNT) - mean * mean;
        float sc   = pG[tid] * rsqrtf(var + BN_EPS);
        sm_sc[tid] = sc;
        sm_sh[tid] = pB[tid] - mean * sc;
    }

    // stage-B decode (C==32 vectorized): thread = (pt, cq, b)
    const int ptB = tid >> 4;          // 0..15
    const int rB  = tid & 15;
    const int cqB = rB >> 3;           // 0..1
    const int bB  = rB & 7;            // 0..7

    // stage-C decode: 4 col-tiles x 2 row-halves
    const int colt = (tid >> 5) & 3;   // warp % 4 (uniform)
    const int rowh = tid >> 7;         // 0/1
    const int lane = tid & 31;

    float ssum[OT], ssq[OT];
#pragma unroll
    for (int j = 0; j < OT; ++j) { ssum[j] = 0.f; ssq[j] = 0.f; }

    for (int g = g0; g < NG; g += gstride) {
        const int n0 = g * P;
        if (tid < P * 9) sm_idx[tid] = nbr[n0 * 9 + tid];
        for (int e = tid; e < P * 81; e += 256) {
            int pt = e / 81, r = e - pt * 81, k = r / 9, t = r - k * 9;
            sm_a[pt * 108 + k * 12 + t] = A[(size_t)n0 * 81 + e];
        }
        __syncthreads();

        ull acc[RT][OT / 2];
#pragma unroll
        for (int i = 0; i < RT; ++i)
#pragma unroll
            for (int j = 0; j < OT / 2; ++j)
                acc[i][j] = pack2(sm_bias[colt * OT + 2 * j], sm_bias[colt * OT + 2 * j + 1]);

#pragma unroll 1
        for (int q = 0; q < NQ; ++q) {
            // ---- stage B pass q: vectorized gather + reduce ----
            if (C == 32) {
                const int c0 = q * CQ + cqB * 4;
                const int* ip = sm_idx + ptB * 9;
                const float* ap = sm_a + ptB * 108;

                float4 xr[9];
#pragma unroll
                for (int k = 0; k < 9; ++k)
                    xr[k] = *(const float4*)(xin + (size_t)ip[k] * BCin + bB * C + c0);
                if (BNIN) {
                    float4 sc4 = *(const float4*)(sm_sc + c0);
                    float4 sh4 = *(const float4*)(sm_sh + c0);
#pragma unroll
                    for (int k = 0; k < 9; ++k) {
                        xr[k].x = fmaxf(0.f, fmaf(xr[k].x, sc4.x, sh4.x));
                        xr[k].y = fmaxf(0.f, fmaf(xr[k].y, sc4.y, sh4.y));
                        xr[k].z = fmaxf(0.f, fmaf(xr[k].z, sc4.z, sh4.z));
                        xr[k].w = fmaxf(0.f, fmaf(xr[k].w, sc4.w, sh4.w));
                    }
                }
                ull ac[4][4]; float ac8[4];
#pragma unroll
                for (int cc = 0; cc < 4; ++cc) {
                    ac[cc][0] = 0; ac[cc][1] = 0; ac[cc][2] = 0; ac[cc][3] = 0; ac8[cc] = 0.f;
                }
#pragma unroll
                for (int k = 0; k < 9; ++k) {
                    const ulonglong2* a2 = (const ulonglong2*)(ap + k * 12);
                    ulonglong2 a03 = a2[0], a47 = a2[1];
                    float a8 = ap[k * 12 + 8];
                    const float* xv = (const float*)&xr[k];
#pragma unroll
                    for (int cc = 0; cc < 4; ++cc) {
                        float xk = xv[cc];
                        ull xx = pack2(xk, xk);
                        ac[cc][0] = ffma2(xx, a03.x, ac[cc][0]);
                        ac[cc][1] = ffma2(xx, a03.y, ac[cc][1]);
                        ac[cc][2] = ffma2(xx, a47.x, ac[cc][2]);
                        ac[cc][3] = ffma2(xx, a47.y, ac[cc][3]);
                        ac8[cc] = fmaf(xk, a8, ac8[cc]);
                    }
                }
#pragma unroll
                for (int cc = 0; cc < 4; ++cc) {
                    float* gp = sm_G + ((cqB * 4 + cc) * 9) * RS + ptB * 8 + bB;
                    float v0,v1,v2,v3,v4,v5,v6,v7;
                    unpack2(ac[cc][0], v0, v1); unpack2(ac[cc][1], v2, v3);
                    unpack2(ac[cc][2], v4, v5); unpack2(ac[cc][3], v6, v7);
                    gp[0*RS]=v0; gp[1*RS]=v1; gp[2*RS]=v2; gp[3*RS]=v3;
                    gp[4*RS]=v4; gp[5*RS]=v5; gp[6*RS]=v6; gp[7*RS]=v7;
                    gp[8*RS]=ac8[cc];
                }
            } else {  // C == 3, NQ == 1
#pragma unroll
                for (int it = tid; it < P * 24; it += 256) {
                    const int pt = it / 24, bc = it - pt * 24;
                    const int b = bc / 3, c = bc - b * 3;
                    const float* ap = sm_a + pt * 108;
                    const int* ip = sm_idx + pt * 9;
                    float xr[9];
#pragma unroll
                    for (int k = 0; k < 9; ++k) xr[k] = xin[ip[k] * BCin + bc];
                    ull ac01 = 0, ac23 = 0, ac45 = 0, ac67 = 0; float ac8 = 0.f;
#pragma unroll
                    for (int k = 0; k < 9; ++k) {
                        ull xx = pack2(xr[k], xr[k]);
                        const ulonglong2* a2 = (const ulonglong2*)(ap + k * 12);
                        ulonglong2 a03 = a2[0], a47 = a2[1];
                        ac01 = ffma2(xx, a03.x, ac01);
                        ac23 = ffma2(xx, a03.y, ac23);
                        ac45 = ffma2(xx, a47.x, ac45);
                        ac67 = ffma2(xx, a47.y, ac67);
                        ac8 = fmaf(xr[k], ap[k * 12 + 8], ac8);
                    }
                    float* gp = sm_G + (c * 9) * RS + pt * 8 + b;
                    float v0,v1,v2,v3,v4,v5,v6,v7;
                    unpack2(ac01, v0, v1); unpack2(ac23, v2, v3);
                    unpack2(ac45, v4, v5); unpack2(ac67, v6, v7);
                    gp[0*RS]=v0; gp[1*RS]=v1; gp[2*RS]=v2; gp[3*RS]=v3;
                    gp[4*RS]=v4; gp[5*RS]=v5; gp[6*RS]=v6; gp[7*RS]=v7;
                    gp[8*RS]=ac8;
                }
            }
            __syncthreads();   // G slice ready

            // ---- stage C pass q: RT=2 rows x OT=8 cols ----
            {
                const float* Wq = sm_Wt + (q * CTQ) * ONB + colt * OT;   // warp-uniform
                const float* Gq = sm_G + rowh * 64 + lane * 2;
#pragma unroll 4
                for (int ctl = 0; ctl < CTQ; ++ctl) {
                    ulonglong2 wA = *(const ulonglong2*)(Wq + ctl * ONB);        // broadcast
                    ulonglong2 wB = *(const ulonglong2*)(Wq + ctl * ONB + 4);    // broadcast
                    float2 gv = *(const float2*)(Gq + ctl * RS);
                    ull gg0 = pack2(gv.x, gv.x), gg1 = pack2(gv.y, gv.y);
                    acc[0][0] = ffma2(gg0, wA.x, acc[0][0]);
                    acc[0][1] = ffma2(gg0, wA.y, acc[0][1]);
                    acc[0][2] = ffma2(gg0, wB.x, acc[0][2]);
                    acc[0][3] = ffma2(gg0, wB.y, acc[0][3]);
                    acc[1][0] = ffma2(gg1, wA.x, acc[1][0]);
                    acc[1][1] = ffma2(gg1, wA.y, acc[1][1]);
                    acc[1][2] = ffma2(gg1, wB.x, acc[1][2]);
                    acc[1][3] = ffma2(gg1, wB.y, acc[1][3]);
                }
            }
            __syncthreads();   // G slice consumed
        }

        // ---- write out + stats ----
#pragma unroll
        for (int i = 0; i < RT; ++i) {
            int row = rowh * 64 + lane * 2 + i, pt = row >> 3, b = row & 7;
            float* yp = yout + (size_t)(n0 + pt) * (BB * OFULL) + b * OFULL + obase + colt * OT;
            float v[OT];
#pragma unroll
            for (int j = 0; j < OT / 2; ++j) unpack2(acc[i][j], v[2 * j], v[2 * j + 1]);
            ((float4*)yp)[0] = make_float4(v[0], v[1], v[2], v[3]);
            ((float4*)yp)[1] = make_float4(v[4], v[5], v[6], v[7]);
#pragma unroll
            for (int j = 0; j < OT; ++j) {
                ssum[j] += v[j];
                ssq[j] = fmaf(v[j], v[j], ssq[j]);
            }
        }
    }

    // stats merge: warp shuffle (colt uniform), lane0 -> smem -> global
#pragma unroll
    for (int j = 0; j < OT; ++j) {
#pragma unroll
        for (int d = 16; d > 0; d >>= 1) {
            ssum[j] += __shfl_xor_sync(0xFFFFFFFFu, ssum[j], d);
            ssq[j]  += __shfl_xor_sync(0xFFFFFFFFu, ssq[j], d);
        }
    }
    if (lane == 0) {
#pragma unroll
        for (int j = 0; j < OT; ++j) {
            atomicAdd(sm_sum + colt * OT + j, ssum[j]);
            atomicAdd(sm_sq  + colt * OT + j, ssq[j]);
        }
    }
    __syncthreads();
    if (tid < ONB) {
        atomicAdd(gSum + obase + tid, sm_sum[tid]);
        atomicAdd(gSq  + obase + tid, sm_sq[tid]);
    }
}

// ---------------- max pool (+BN3+ReLU) + transpose to (8,64,N3) ----------------
__global__ void k_pool(const float* __restrict__ x3, const int* __restrict__ pidx,
                       float* __restrict__ out,
                       const float* __restrict__ gS, const float* __restrict__ gQ,
                       const float* __restrict__ gamma, const float* __restrict__ beta) {
    __shared__ float smp[16 * 513];
    int tid = threadIdx.x;
    int base = blockIdx.x * 16;
    int o = tid & 63;
    float mean = gS[o] * (1.f / CNT);
    float var  = gQ[o] * (1.f / CNT) - mean * mean;
    float sc   = gamma[o] * rsqrtf(var + BN_EPS);
    float sh   = beta[o] - mean * sc;
    bool pos = (sc >= 0.f);
    float init = pos ? -3.4e38f : 3.4e38f;
    for (int i = 0; i < 16; ++i) {
        int n3 = base + i;
        float m0 = init, m1 = init;
#pragma unroll
        for (int k = 0; k < 9; ++k) {
            const float* row = x3 + (size_t)pidx[n3 * 9 + k] * 512;
            float r0 = row[tid], r1 = row[tid + 256];
            if (pos) { m0 = fmaxf(m0, r0); m1 = fmaxf(m1, r1); }
            else     { m0 = fminf(m0, r0); m1 = fminf(m1, r1); }
        }
        smp[i * 513 + tid]       = fmaxf(0.f, fmaf(m0, sc, sh));
        smp[i * 513 + tid + 256] = fmaxf(0.f, fmaf(m1, sc, sh));
    }
    __syncthreads();
#pragma unroll
    for (int h = 0; h < 2; ++h) {
        int bc = tid + h * 256;
        float4 t4[4];
        float* t = (float*)t4;
#pragma unroll
        for (int i = 0; i < 16; ++i) t[i] = smp[i * 513 + bc];
        float4* dst = (float4*)(out + (size_t)bc * N3V + base);
#pragma unroll
        for (int q = 0; q < 4; ++q) dst[q] = t4[q];
    }
}

static constexpr size_t layer_smem(int C, int NQ, int RS) {
    int CT = C * 9;
    int CTQ = (C / NQ) * 9;
    return (size_t)4 * (CT * 32 + CTQ * RS + 16 * 108 + 3 * 32 + 2 * C + 16 * 9);
}

extern "C" void kernel_launch(void* const* d_in, const int* in_sizes, int n_in,
                              void* d_out, int out_size) {
    const float* x    = (const float*)d_in[0];
    const int*   nbr1 = (const int*)d_in[1];
    const float* off1 = (const float*)d_in[2];
    const int*   nbr2 = (const int*)d_in[3];
    const float* off2 = (const float*)d_in[4];
    const int*   pidx = (const int*)d_in[5];
    const float* Wh   = (const float*)d_in[6];
    const float* bh   = (const float*)d_in[7];
    const float* Wo   = (const float*)d_in[8];
    const float* bo   = (const float*)d_in[9];
    const float* W1   = (const float*)d_in[10];
    const float* b1   = (const float*)d_in[11];
    const float* W2   = (const float*)d_in[12];
    const float* b2   = (const float*)d_in[13];
    const float* W3   = (const float*)d_in[14];
    const float* b3   = (const float*)d_in[15];
    const float* g1   = (const float*)d_in[16];
    const float* be1  = (const float*)d_in[17];
    const float* g2   = (const float*)d_in[18];
    const float* be2  = (const float*)d_in[19];
    const float* g3   = (const float*)d_in[20];
    const float* be3  = (const float*)d_in[21];
    float* out = (float*)d_out;

    float *xt1, *A1, *A2, *y1, *y2, *y3, *stats;
    cudaGetSymbolAddress((void**)&xt1, d_xt1);
    cudaGetSymbolAddress((void**)&A1, d_A1);
    cudaGetSymbolAddress((void**)&A2, d_A2);
    cudaGetSymbolAddress((void**)&y1, d_y1);
    cudaGetSymbolAddress((void**)&y2, d_y2);
    cudaGetSymbolAddress((void**)&y3, d_y3);
    cudaGetSymbolAddress((void**)&stats, d_stats);

    const size_t sm1 = layer_smem(3, 1, 132);
    const size_t sm2 = layer_smem(32, 4, 132);
    cudaFuncSetAttribute((const void*)k_layer<3, 32, 1, 132, false, false>,  cudaFuncAttributeMaxDynamicSharedMemorySize, (int)sm1);
    cudaFuncSetAttribute((const void*)k_layer<32, 32, 4, 132, true, false>,  cudaFuncAttributeMaxDynamicSharedMemorySize, (int)sm2);
    cudaFuncSetAttribute((const void*)k_layer<32, 64, 4, 132, true, true>,   cudaFuncAttributeMaxDynamicSharedMemorySize, (int)sm2);

    k_transpose<<<(N1V + 255) / 256, 256>>>(x, xt1, stats);
    k_mlp2<<<(2 * N2V * 9 + 127) / 128, 128>>>(off1, off2, Wh, bh, Wo, bo, A1, A2);

    // layer1: one group per CTA, high occupancy
    k_layer<3, 32, 1, 132, false, false><<<784, 256, sm1>>>(
        xt1, A1, nbr1, W1, b1, y1, stats + 0, stats + 32,
        nullptr, nullptr, nullptr, nullptr);
    // layer2: NQ=4, float4 gather, OT=8/RT=2 stage C, 2 CTAs/SM
    k_layer<32, 32, 4, 132, true, false><<<296, 256, sm2>>>(
        y1, A2, nbr2, W2, b2, y2, stats + 64, stats + 96,
        stats + 0, stats + 32, g1, be1);
    // layer3: SPLIT2 (32 cols/CTA), same shape
    k_layer<32, 64, 4, 132, true, true><<<592, 256, sm2>>>(
        y2, A2, nbr2, W3, b3, y3, stats + 128, stats + 192,
        stats + 64, stats + 96, g2, be2);

    k_pool<<<N3V / 16, 256>>>(y3, pidx, out, stats + 128, stats + 192, g3, be3);
}

// round 15
// speedup vs baseline: 1.2343x; 1.2343x over previous
#include <cuda_runtime.h>

#define BB 8
#define N1V 50176
#define N2V 12544
#define N3V 3136
#define CNT 100352          // BB*N2V
#define BN_EPS 1e-5f

typedef unsigned long long ull;

// ---------------- scratch ----------------
__device__ float d_xt1[N1V * 24];
__device__ float d_A1[N2V * 81];
__device__ float d_A2[N2V * 81];
__device__ float d_y1[N2V * 256];   // RAW outputs; BN fused into consumers
__device__ float d_y2[N2V * 256];
__device__ float d_y3[N2V * 512];
__device__ float d_stats[256];      // s1[32] q1[32] s2[32] q2[32] s3[64] q3[64]
// pre-transposed weights [ct][o] (float4 arrays for 16B alignment)
__device__ float4 d_Wt1[27 * 32 / 4];
__device__ float4 d_Wt2[288 * 32 / 4];
__device__ float4 d_Wt3[288 * 64 / 4];

// ---------------- f32x2 helpers ----------------
__device__ __forceinline__ ull pack2(float lo, float hi) {
    ull r; asm("mov.b64 %0, {%1, %2};" : "=l"(r) : "f"(lo), "f"(hi)); return r;
}
__device__ __forceinline__ void unpack2(ull v, float& lo, float& hi) {
    asm("mov.b64 {%0, %1}, %2;" : "=f"(lo), "=f"(hi) : "l"(v));
}
__device__ __forceinline__ ull ffma2(ull a, ull b, ull c) {
    ull d; asm("fma.rn.f32x2 %0, %1, %2, %3;" : "=l"(d) : "l"(a), "l"(b), "l"(c)); return d;
}

// ---------------- transpose x (8,3,N1) -> xt1[n][24]; block 0 zeros stats ----------------
__global__ void k_transpose(const float* __restrict__ x, float* __restrict__ xt,
                            float* __restrict__ stats) {
    int tid = threadIdx.x;
    if (blockIdx.x == 0) stats[tid] = 0.f;
    int n = blockIdx.x * 256 + tid;
    if (n >= N1V) return;
    float4 t4[6];
    float* t = (float*)t4;
#pragma unroll
    for (int bc = 0; bc < 24; ++bc) t[bc] = x[bc * N1V + n];
    float4* dst = (float4*)(xt + n * 24);
#pragma unroll
    for (int i = 0; i < 6; ++i) dst[i] = t4[i];
}

// ---------------- one-time weight transpose ----------------
__global__ void k_prep(const float* __restrict__ W1, const float* __restrict__ W2,
                       const float* __restrict__ W3,
                       float* __restrict__ Wt1, float* __restrict__ Wt2,
                       float* __restrict__ Wt3) {
    int i = blockIdx.x * 256 + threadIdx.x;
    if (i < 27 * 32)  { int ct = i / 32, o = i - ct * 32; Wt1[i] = W1[o * 27 + ct]; }
    if (i < 288 * 32) { int ct = i / 32, o = i - ct * 32; Wt2[i] = W2[o * 288 + ct]; }
    if (i < 288 * 64) { int ct = i / 64, o = i - ct * 64; Wt3[i] = W3[o * 288 + ct]; }
}

// ---------------- weight MLP (both offsets, one launch) ----------------
__global__ void __launch_bounds__(128) k_mlp2(const float* __restrict__ off1,
                      const float* __restrict__ off2,
                      const float* __restrict__ Wh, const float* __restrict__ bh,
                      const float* __restrict__ Wo, const float* __restrict__ bo,
                      float* __restrict__ A1, float* __restrict__ A2) {
    __shared__ float sWh[64], sbh[32], sWo[288], sbo[9];
    int tid = threadIdx.x;
    if (tid < 64) sWh[tid] = Wh[tid];
    if (tid < 32) sbh[tid] = bh[tid];
    for (int e = tid; e < 288; e += 128) sWo[e] = Wo[e];
    if (tid < 9) sbo[tid] = bo[tid];
    __syncthreads();
    int id = blockIdx.x * 128 + tid;
    const int T9 = N2V * 9;
    if (id >= 2 * T9) return;
    const float* off = (id < T9) ? off1 : off2;
    float* A = (id < T9) ? A1 : A2;
    int lid = (id < T9) ? id : id - T9;
    float2 o2 = ((const float2*)off)[lid];
    float h[32];
#pragma unroll
    for (int j = 0; j < 32; ++j)
        h[j] = fmaxf(0.f, fmaf(o2.x, sWh[j], fmaf(o2.y, sWh[32 + j], sbh[j])));
#pragma unroll
    for (int t = 0; t < 9; ++t) {
        float acc = sbo[t];
#pragma unroll
        for (int j = 0; j < 32; ++j) acc = fmaf(h[j], sWo[j * 9 + t], acc);
        A[lid * 9 + t] = acc;
    }
}

// ---------------- fused interp-conv layer, streamed-W ct-split passes ----------------
// Single CTA owns ALL O outputs. W pre-transposed [ct][O] in GLOBAL; per pass the
// CTQ x O slice is copied (dense) into smem, fenced by the existing pass barriers.
// Stage B: float4 gather, thread=(pt,cq,b), k-streamed (low regs). G TRANSPOSED
// sm_G[ct*RS+row]. Stage C: 8 warps = O/OT col-tiles, RT=4 rows/lane
// (W warp-uniform broadcast, G LDS.128).
template <int C, int O, int OT, int NQ, int RS, int MINB, bool BNIN>
__global__ void __launch_bounds__(256, MINB) k_layer(
    const float* __restrict__ xin, const float* __restrict__ A,
    const int* __restrict__ nbr, const float* __restrict__ Wt,
    const float* __restrict__ bias, float* __restrict__ yout,
    float* __restrict__ gSum, float* __restrict__ gSq,
    const float* __restrict__ pS, const float* __restrict__ pQ,
    const float* __restrict__ pG, const float* __restrict__ pB)
{
    constexpr int RT = 4;
    constexpr int OTH = OT / 2;
    constexpr int P = 16;
    constexpr int BCin = BB * C;
    constexpr int CQ = C / NQ;         // 8 for C=32
    constexpr int CTQ = CQ * 9;
    constexpr int NG = N2V / P;        // 784

    static_assert(O / OT == 8, "8 warps = col tiles");

    extern __shared__ float sm[];
    float* sm_W   = sm;                       // CTQ*O  (current slice, ct-local)
    float* sm_G   = sm_W + CTQ * O;           // CTQ*RS
    float* sm_a   = sm_G + CTQ * RS;          // P*108
    float* sm_bias= sm_a + P * 108;           // O
    float* sm_sum = sm_bias + O;              // O
    float* sm_sq  = sm_sum + O;               // O
    float* sm_sc  = sm_sq + O;                // C
    float* sm_sh  = sm_sc + C;                // C
    int*   sm_idx = (int*)(sm_sh + C);        // P*9

    const int tid = threadIdx.x;

    if (tid < O) { sm_bias[tid] = bias[tid]; sm_sum[tid] = 0.f; sm_sq[tid] = 0.f; }
    if (BNIN && tid < C) {
        float mean = pS[tid] * (1.f / CNT);
        float var  = pQ[tid] * (1.f / CNT) - mean * mean;
        float sc   = pG[tid] * rsqrtf(var + BN_EPS);
        sm_sc[tid] = sc;
        sm_sh[tid] = pB[tid] - mean * sc;
    }

    // stage-B decode (C==32): thread = (pt, cq, b)
    const int ptB = tid >> 4;          // 0..15
    const int rB  = tid & 15;
    const int cqB = rB >> 3;           // 0..1
    const int bB  = rB & 7;            // 0..7

    // stage-C decode: 8 col-tiles, lane -> RT rows
    const int colt = tid >> 5;         // warp id (uniform)
    const int lane = tid & 31;

    float ssum[OT], ssq[OT];
#pragma unroll
    for (int j = 0; j < OT; ++j) { ssum[j] = 0.f; ssq[j] = 0.f; }

    for (int g = blockIdx.x; g < NG; g += gridDim.x) {
        const int n0 = g * P;
        if (tid < P * 9) sm_idx[tid] = nbr[n0 * 9 + tid];
        for (int e = tid; e < P * 81; e += 256) {
            int pt = e / 81, r = e - pt * 81, k = r / 9, t = r - k * 9;
            sm_a[pt * 108 + k * 12 + t] = A[(size_t)n0 * 81 + e];
        }
        __syncthreads();

        ull acc[RT][OTH];
#pragma unroll
        for (int i = 0; i < RT; ++i)
#pragma unroll
            for (int j = 0; j < OTH; ++j)
                acc[i][j] = pack2(sm_bias[colt * OT + 2 * j], sm_bias[colt * OT + 2 * j + 1]);

#pragma unroll 1
        for (int q = 0; q < NQ; ++q) {
            // ---- W slice copy (dense; fenced by pass barriers) ----
            {
                const float4* src = (const float4*)(Wt + (size_t)q * CTQ * O);
                float4* dst = (float4*)sm_W;
                for (int e = tid; e < CTQ * O / 4; e += 256) dst[e] = src[e];
            }
            // ---- stage B pass q ----
            if (C == 32) {
                const int c0 = q * CQ + cqB * 4;
                const float* xb = xin + bB * C + c0;
                const int* ip = sm_idx + ptB * 9;
                const float* ap = sm_a + ptB * 108;
                float4 sc4, sh4;
                if (BNIN) { sc4 = *(const float4*)(sm_sc + c0); sh4 = *(const float4*)(sm_sh + c0); }
                ull ac0[4], ac1[4], ac2[4], ac3[4]; float ac8[4];
#pragma unroll
                for (int cc = 0; cc < 4; ++cc) { ac0[cc]=0; ac1[cc]=0; ac2[cc]=0; ac3[cc]=0; ac8[cc]=0.f; }
#pragma unroll
                for (int k = 0; k < 9; ++k) {
                    float4 xk = *(const float4*)(xb + (size_t)ip[k] * BCin);
                    if (BNIN) {
                        xk.x = fmaxf(0.f, fmaf(xk.x, sc4.x, sh4.x));
                        xk.y = fmaxf(0.f, fmaf(xk.y, sc4.y, sh4.y));
                        xk.z = fmaxf(0.f, fmaf(xk.z, sc4.z, sh4.z));
                        xk.w = fmaxf(0.f, fmaf(xk.w, sc4.w, sh4.w));
                    }
                    const ulonglong2* a2 = (const ulonglong2*)(ap + k * 12);
                    ulonglong2 a03 = a2[0], a47 = a2[1];
                    float a8 = ap[k * 12 + 8];
                    float xv[4] = {xk.x, xk.y, xk.z, xk.w};
#pragma unroll
                    for (int cc = 0; cc < 4; ++cc) {
                        ull xx = pack2(xv[cc], xv[cc]);
                        ac0[cc] = ffma2(xx, a03.x, ac0[cc]);
                        ac1[cc] = ffma2(xx, a03.y, ac1[cc]);
                        ac2[cc] = ffma2(xx, a47.x, ac2[cc]);
                        ac3[cc] = ffma2(xx, a47.y, ac3[cc]);
                        ac8[cc] = fmaf(xv[cc], a8, ac8[cc]);
                    }
                }
#pragma unroll
                for (int cc = 0; cc < 4; ++cc) {
                    float* gp = sm_G + ((cqB * 4 + cc) * 9) * RS + ptB * 8 + bB;
                    float v0,v1,v2,v3,v4,v5,v6,v7;
                    unpack2(ac0[cc], v0, v1); unpack2(ac1[cc], v2, v3);
                    unpack2(ac2[cc], v4, v5); unpack2(ac3[cc], v6, v7);
                    gp[0*RS]=v0; gp[1*RS]=v1; gp[2*RS]=v2; gp[3*RS]=v3;
                    gp[4*RS]=v4; gp[5*RS]=v5; gp[6*RS]=v6; gp[7*RS]=v7;
                    gp[8*RS]=ac8[cc];
                }
            } else {  // C == 3, NQ == 1
#pragma unroll
                for (int it = tid; it < P * 24; it += 256) {
                    const int pt = it / 24, bc = it - pt * 24;
                    const int b = bc / 3, c = bc - b * 3;
                    const float* ap = sm_a + pt * 108;
                    const int* ip = sm_idx + pt * 9;
                    float xr[9];
#pragma unroll
                    for (int k = 0; k < 9; ++k) xr[k] = xin[ip[k] * BCin + bc];
                    ull ac01 = 0, ac23 = 0, ac45 = 0, ac67 = 0; float ac8 = 0.f;
#pragma unroll
                    for (int k = 0; k < 9; ++k) {
                        ull xx = pack2(xr[k], xr[k]);
                        const ulonglong2* a2 = (const ulonglong2*)(ap + k * 12);
                        ulonglong2 a03 = a2[0], a47 = a2[1];
                        ac01 = ffma2(xx, a03.x, ac01);
                        ac23 = ffma2(xx, a03.y, ac23);
                        ac45 = ffma2(xx, a47.x, ac45);
                        ac67 = ffma2(xx, a47.y, ac67);
                        ac8 = fmaf(xr[k], ap[k * 12 + 8], ac8);
                    }
                    float* gp = sm_G + (c * 9) * RS + pt * 8 + b;
                    float v0,v1,v2,v3,v4,v5,v6,v7;
                    unpack2(ac01, v0, v1); unpack2(ac23, v2, v3);
                    unpack2(ac45, v4, v5); unpack2(ac67, v6, v7);
                    gp[0*RS]=v0; gp[1*RS]=v1; gp[2*RS]=v2; gp[3*RS]=v3;
                    gp[4*RS]=v4; gp[5*RS]=v5; gp[6*RS]=v6; gp[7*RS]=v7;
                    gp[8*RS]=ac8;
                }
            }
            __syncthreads();   // G slice + W slice ready

            // ---- stage C pass q: RT=4 rows x OT cols ----
            {
                const float* Wq = sm_W + colt * OT;    // warp-uniform
                const float* Gq = sm_G + lane * RT;
#pragma unroll 4
                for (int ctl = 0; ctl < CTQ; ++ctl) {
                    ull w[OTH];
                    {
                        ulonglong2 wA = *(const ulonglong2*)(Wq + (size_t)ctl * O);     // broadcast
                        w[0] = wA.x; w[1] = wA.y;
                        if (OTH > 2) {
                            ulonglong2 wB = *(const ulonglong2*)(Wq + (size_t)ctl * O + 4);
                            w[2] = wB.x; w[3] = wB.y;
                        }
                    }
                    float4 gv = *(const float4*)(Gq + ctl * RS);
                    ull gg0 = pack2(gv.x, gv.x), gg1 = pack2(gv.y, gv.y);
                    ull gg2 = pack2(gv.z, gv.z), gg3 = pack2(gv.w, gv.w);
#pragma unroll
                    for (int j = 0; j < OTH; ++j) {
                        acc[0][j] = ffma2(gg0, w[j], acc[0][j]);
                        acc[1][j] = ffma2(gg1, w[j], acc[1][j]);
                        acc[2][j] = ffma2(gg2, w[j], acc[2][j]);
                        acc[3][j] = ffma2(gg3, w[j], acc[3][j]);
                    }
                }
            }
            __syncthreads();   // G + W slices consumed
        }

        // ---- write out + stats ----
#pragma unroll
        for (int i = 0; i < RT; ++i) {
            int row = lane * RT + i, pt = row >> 3, b = row & 7;
            float* yp = yout + (size_t)(n0 + pt) * (BB * O) + b * O + colt * OT;
            float v[OT];
#pragma unroll
            for (int j = 0; j < OTH; ++j) unpack2(acc[i][j], v[2 * j], v[2 * j + 1]);
#pragma unroll
            for (int qv = 0; qv < OT / 4; ++qv)
                ((float4*)yp)[qv] = make_float4(v[4 * qv], v[4 * qv + 1], v[4 * qv + 2], v[4 * qv + 3]);
#pragma unroll
            for (int j = 0; j < OT; ++j) {
                ssum[j] += v[j];
                ssq[j] = fmaf(v[j], v[j], ssq[j]);
            }
        }
    }

    // stats merge: warp shuffle (colt uniform), lane0 -> smem -> global
#pragma unroll
    for (int j = 0; j < OT; ++j) {
#pragma unroll
        for (int d = 16; d > 0; d >>= 1) {
            ssum[j] += __shfl_xor_sync(0xFFFFFFFFu, ssum[j], d);
            ssq[j]  += __shfl_xor_sync(0xFFFFFFFFu, ssq[j], d);
        }
    }
    if (lane == 0) {
#pragma unroll
        for (int j = 0; j < OT; ++j) {
            atomicAdd(sm_sum + colt * OT + j, ssum[j]);
            atomicAdd(sm_sq  + colt * OT + j, ssq[j]);
        }
    }
    __syncthreads();
    if (tid < O) {
        atomicAdd(gSum + tid, sm_sum[tid]);
        atomicAdd(gSq  + tid, sm_sq[tid]);
    }
}

// ---------------- max pool (+BN3+ReLU) + transpose to (8,64,N3) ----------------
__global__ void k_pool(const float* __restrict__ x3, const int* __restrict__ pidx,
                       float* __restrict__ out,
                       const float* __restrict__ gS, const float* __restrict__ gQ,
                       const float* __restrict__ gamma, const float* __restrict__ beta) {
    __shared__ float smp[16 * 513];
    int tid = threadIdx.x;
    int base = blockIdx.x * 16;
    int o = tid & 63;
    float mean = gS[o] * (1.f / CNT);
    float var  = gQ[o] * (1.f / CNT) - mean * mean;
    float sc   = gamma[o] * rsqrtf(var + BN_EPS);
    float sh   = beta[o] - mean * sc;
    bool pos = (sc >= 0.f);
    float init = pos ? -3.4e38f : 3.4e38f;
    for (int i = 0; i < 16; ++i) {
        int n3 = base + i;
        float m0 = init, m1 = init;
#pragma unroll
        for (int k = 0; k < 9; ++k) {
            const float* row = x3 + (size_t)pidx[n3 * 9 + k] * 512;
            float r0 = row[tid], r1 = row[tid + 256];
            if (pos) { m0 = fmaxf(m0, r0); m1 = fmaxf(m1, r1); }
            else     { m0 = fminf(m0, r0); m1 = fminf(m1, r1); }
        }
        smp[i * 513 + tid]       = fmaxf(0.f, fmaf(m0, sc, sh));
        smp[i * 513 + tid + 256] = fmaxf(0.f, fmaf(m1, sc, sh));
    }
    __syncthreads();
#pragma unroll
    for (int h = 0; h < 2; ++h) {
        int bc = tid + h * 256;
        float4 t4[4];
        float* t = (float*)t4;
#pragma unroll
        for (int i = 0; i < 16; ++i) t[i] = smp[i * 513 + bc];
        float4* dst = (float4*)(out + (size_t)bc * N3V + base);
#pragma unroll
        for (int q = 0; q < 4; ++q) dst[q] = t4[q];
    }
}

static constexpr size_t layer_smem(int C, int O, int NQ, int RS) {
    int CTQ = (C / NQ) * 9;
    return (size_t)4 * (CTQ * O + CTQ * RS + 16 * 108 + 3 * O + 2 * C + 16 * 9);
}

extern "C" void kernel_launch(void* const* d_in, const int* in_sizes, int n_in,
                              void* d_out, int out_size) {
    const float* x    = (const float*)d_in[0];
    const int*   nbr1 = (const int*)d_in[1];
    const float* off1 = (const float*)d_in[2];
    const int*   nbr2 = (const int*)d_in[3];
    const float* off2 = (const float*)d_in[4];
    const int*   pidx = (const int*)d_in[5];
    const float* Wh   = (const float*)d_in[6];
    const float* bh   = (const float*)d_in[7];
    const float* Wo   = (const float*)d_in[8];
    const float* bo   = (const float*)d_in[9];
    const float* W1   = (const float*)d_in[10];
    const float* b1   = (const float*)d_in[11];
    const float* W2   = (const float*)d_in[12];
    const float* b2   = (const float*)d_in[13];
    const float* W3   = (const float*)d_in[14];
    const float* b3   = (const float*)d_in[15];
    const float* g1   = (const float*)d_in[16];
    const float* be1  = (const float*)d_in[17];
    const float* g2   = (const float*)d_in[18];
    const float* be2  = (const float*)d_in[19];
    const float* g3   = (const float*)d_in[20];
    const float* be3  = (const float*)d_in[21];
    float* out = (float*)d_out;

    float *xt1, *A1, *A2, *y1, *y2, *y3, *stats, *Wt1, *Wt2, *Wt3;
    cudaGetSymbolAddress((void**)&xt1, d_xt1);
    cudaGetSymbolAddress((void**)&A1, d_A1);
    cudaGetSymbolAddress((void**)&A2, d_A2);
    cudaGetSymbolAddress((void**)&y1, d_y1);
    cudaGetSymbolAddress((void**)&y2, d_y2);
    cudaGetSymbolAddress((void**)&y3, d_y3);
    cudaGetSymbolAddress((void**)&stats, d_stats);
    cudaGetSymbolAddress((void**)&Wt1, d_Wt1);
    cudaGetSymbolAddress((void**)&Wt2, d_Wt2);
    cudaGetSymbolAddress((void**)&Wt3, d_Wt3);

    const size_t sm1 = layer_smem(3, 32, 1, 132);    // ~25.6 KB
    const size_t sm2 = layer_smem(32, 32, 4, 132);   // ~55.4 KB -> 3 CTAs/SM
    const size_t sm3 = layer_smem(32, 64, 4, 132);   // ~65.0 KB -> 2 CTAs/SM
    cudaFuncSetAttribute((const void*)k_layer<3, 32, 4, 1, 132, 3, false>, cudaFuncAttributeMaxDynamicSharedMemorySize, (int)sm1);
    cudaFuncSetAttribute((const void*)k_layer<32, 32, 4, 4, 132, 3, true>, cudaFuncAttributeMaxDynamicSharedMemorySize, (int)sm2);
    cudaFuncSetAttribute((const void*)k_layer<32, 64, 8, 4, 132, 2, true>, cudaFuncAttributeMaxDynamicSharedMemorySize, (int)sm3);

    k_transpose<<<(N1V + 255) / 256, 256>>>(x, xt1, stats);
    k_prep<<<72, 256>>>(W1, W2, W3, (float*)Wt1, (float*)Wt2, (float*)Wt3);
    k_mlp2<<<(2 * N2V * 9 + 127) / 128, 128>>>(off1, off2, Wh, bh, Wo, bo, A1, A2);

    // layer1: one group per CTA
    k_layer<3, 32, 4, 1, 132, 3, false><<<784, 256, sm1>>>(
        xt1, A1, nbr1, Wt1, b1, y1, stats + 0, stats + 32,
        nullptr, nullptr, nullptr, nullptr);
    // layer2: streamed W, 3 CTAs/SM, float4 gather, OT=4/RT=4
    k_layer<32, 32, 4, 4, 132, 3, true><<<444, 256, sm2>>>(
        y1, A2, nbr2, Wt2, b2, y2, stats + 64, stats + 96,
        stats + 0, stats + 32, g1, be1);
    // layer3: streamed W, FULL O=64 per CTA (no gather duplication), 2 CTAs/SM, OT=8/RT=4
    k_layer<32, 64, 8, 4, 132, 2, true><<<296, 256, sm3>>>(
        y2, A2, nbr2, Wt3, b3, y3, stats + 128, stats + 192,
        stats + 64, stats + 96, g2, be2);

    k_pool<<<N3V / 16, 256>>>(y3, pidx, out, stats + 128, stats + 192, g3, be3);
}